// round 9
// baseline (speedup 1.0000x reference)
#include <cuda_runtime.h>
#include <cuda_bf16.h>

// ---------------- problem constants ----------------
#define Bb      2
#define Cc      192
#define DI      384          // d_inner
#define NS      16           // d_state
#define DR      12           // dt_rank
#define Ls      13824        // 24^3
#define CCn     384          // prefix timesteps from depth branch
#define Lt      14208        // CCn + Ls
#define NM      27648        // B*Ls (GEMM rows)
#define NCHUNK  148
#define CLEN    96           // NCHUNK*CLEN == Lt
#define DOUT    1728         // 12^3

// ---------------- scratch (static device globals; no runtime alloc) ----------------
__device__ float g_x1t  [Bb*DI*Ls];        // (b,d,l)  conv input
__device__ float g_z    [Bb*Ls*DI];        // (b,l,d)  gate input
__device__ float g_xs   [Bb*DI*Lt];        // (b,d,t)  concat sequence
__device__ float g_dxc  [Bb*DI*DOUT];      // (b,d,1728)
__device__ float g_fcacc[Bb*DI*DI];        // (b,j,i) split-K accumulator
__device__ float g_dts  [Bb*DR*Lt];        // (b,r,t)
__device__ float g_BsT  [Bb*Lt*NS];        // (b,t,n)
__device__ float g_CsT  [Bb*Lt*NS];        // (b,t,n)
__device__ float g_delta[Bb*DI*Lt];        // (b,d,t)
__device__ float g_hend [NCHUNK*Bb*DI*NS];
__device__ float g_hinit[NCHUNK*Bb*DI*NS];
__device__ float g_dsum [NCHUNK*Bb*DI];
__device__ float g_y2   [Bb*Ls*DI];        // (b,l,d)
__device__ float g_gate [Bb*Ls*DI];        // (b,l,d)

// ---------------- helpers ----------------
__device__ __forceinline__ float sigmoidf_(float x){ return 1.0f/(1.0f+__expf(-x)); }
__device__ __forceinline__ float siluf_(float x){ return x*sigmoidf_(x); }
__device__ __forceinline__ float softplusf_(float x){
    return fmaxf(x,0.0f) + log1pf(__expf(-fabsf(x)));
}

// ---------------- generic SGEMM: C[m,n] = sum_k A[m,k]*W[n,k] ----------------
// BM=128, BN=64, BK=16, 256 threads, 8x4 microtile.
// EPI: 0 = plain float4 store, 1 = in_proj scatter (x1t / z), 2 = atomicAdd (split-K)
template<int EPI>
__global__ __launch_bounds__(256)
void gemm128x64(const float* __restrict__ A, const float* __restrict__ Bw,
                float* __restrict__ C, int N, int Krow, int Kc,
                long sA, long sB, long sC, int ksplit)
{
    int bz    = blockIdx.z;
    int batch = bz / ksplit;
    int ks    = bz - batch*ksplit;
    long k0   = (long)ks * Kc;

    const float* Ab = A  + batch*sA + (long)blockIdx.y*128*Krow + k0;
    const float* Bc = Bw + batch*sB + (long)blockIdx.x*64 *Krow + k0;

    __shared__ float As[16][128];
    __shared__ float Bs[16][64];

    int tid  = threadIdx.x;
    int lrow = tid >> 2;            // 0..63
    int lk   = (tid & 3) << 2;      // 0,4,8,12
    int tx   = tid & 15;
    int ty   = tid >> 4;

    float acc[8][4];
#pragma unroll
    for (int i=0;i<8;i++)
#pragma unroll
        for (int j=0;j<4;j++) acc[i][j]=0.0f;

    for (int kt = 0; kt < Kc; kt += 16) {
        float4 a0 = *(const float4*)(Ab + (long)lrow     *Krow + kt + lk);
        float4 a1 = *(const float4*)(Ab + (long)(lrow+64)*Krow + kt + lk);
        float4 b0 = *(const float4*)(Bc + (long)lrow     *Krow + kt + lk);
        __syncthreads();
        As[lk+0][lrow]=a0.x; As[lk+1][lrow]=a0.y; As[lk+2][lrow]=a0.z; As[lk+3][lrow]=a0.w;
        As[lk+0][lrow+64]=a1.x; As[lk+1][lrow+64]=a1.y; As[lk+2][lrow+64]=a1.z; As[lk+3][lrow+64]=a1.w;
        Bs[lk+0][lrow]=b0.x; Bs[lk+1][lrow]=b0.y; Bs[lk+2][lrow]=b0.z; Bs[lk+3][lrow]=b0.w;
        __syncthreads();
#pragma unroll
        for (int k=0;k<16;k++){
            float4 av0 = *(const float4*)&As[k][ty*4];
            float4 av1 = *(const float4*)&As[k][64+ty*4];
            float4 bv  = *(const float4*)&Bs[k][tx*4];
            float am[8] = {av0.x,av0.y,av0.z,av0.w, av1.x,av1.y,av1.z,av1.w};
            float bn[4] = {bv.x,bv.y,bv.z,bv.w};
#pragma unroll
            for (int i=0;i<8;i++)
#pragma unroll
                for (int j=0;j<4;j++)
                    acc[i][j] = fmaf(am[i], bn[j], acc[i][j]);
        }
    }

    int mbase = blockIdx.y*128;
    int nbase = blockIdx.x*64 + tx*4;
#pragma unroll
    for (int i=0;i<8;i++){
        int mg = mbase + ((i<4) ? (ty*4+i) : (64+ty*4+(i-4)));
        if (EPI==0){
            float* cp = C + batch*sC + (long)mg*N + nbase;
            float4 v = make_float4(acc[i][0],acc[i][1],acc[i][2],acc[i][3]);
            *(float4*)cp = v;
        } else if (EPI==2){
            float* cp = C + batch*sC + (long)mg*N + nbase;
            atomicAdd(cp+0, acc[i][0]);
            atomicAdd(cp+1, acc[i][1]);
            atomicAdd(cp+2, acc[i][2]);
            atomicAdd(cp+3, acc[i][3]);
        } else { // EPI==1: in_proj scatter
            int b = mg / Ls;
            int l = mg - b*Ls;
#pragma unroll
            for (int j=0;j<4;j++){
                int ng = nbase + j;
                if (ng < DI)  g_x1t[((long)(b*DI+ng))*Ls + l] = acc[i][j];
                else          g_z  [((long)b*Ls + l)*DI + (ng-DI)] = acc[i][j];
            }
        }
    }
}

// ---------------- conv1: depthwise 3x3x3, stride 1, pad 1, + bias + silu -> xs[:, :, CCn:] ----
__global__ __launch_bounds__(256)
void conv1_kernel(const float* __restrict__ w, const float* __restrict__ bias)
{
    int bd   = blockIdx.x;          // b*DI + d
    int d    = bd % DI;
    int slab = blockIdx.y;          // 0/1, 12 z-planes each
    int zbase = slab*12;

    __shared__ float sm[14*576];
    const float* src = g_x1t + (long)bd*Ls;
    int tid = threadIdx.x;

    for (int i=tid; i<14*576; i+=256){
        int zp = i/576;
        int z  = zbase - 1 + zp;
        sm[i] = (z>=0 && z<24) ? src[z*576 + (i - zp*576)] : 0.0f;
    }
    float wr[27];
#pragma unroll
    for (int i=0;i<27;i++) wr[i] = __ldg(w + d*27 + i);
    float cb = __ldg(bias + d);
    __syncthreads();

    float* dst = g_xs + (long)bd*Lt + CCn + zbase*576;
    for (int o=tid; o<12*576; o+=256){
        int ozl = o/576;
        int rem = o - ozl*576;
        int oy  = rem/24;
        int ox  = rem - oy*24;
        float acc = cb;
#pragma unroll
        for (int kz=0;kz<3;kz++){
            const float* p = &sm[(ozl+kz)*576];
#pragma unroll
            for (int ky=0;ky<3;ky++){
                int iy = oy + ky - 1;
                if ((unsigned)iy >= 24u) continue;
#pragma unroll
                for (int kx=0;kx<3;kx++){
                    int ix = ox + kx - 1;
                    if ((unsigned)ix >= 24u) continue;
                    acc = fmaf(p[iy*24+ix], wr[kz*9+ky*3+kx], acc);
                }
            }
        }
        dst[o] = siluf_(acc);
    }
}

// ---------------- conv2: depthwise 3x3x3, stride 2, pad 1, + bias -> g_dxc ----------------
__global__ void conv2_kernel(const float* __restrict__ w, const float* __restrict__ bias)
{
    int idx = blockIdx.x*256 + threadIdx.x;
    if (idx >= Bb*DI*DOUT) return;
    int ox = idx % 12; int t = idx/12;
    int oy = t % 12;   t /= 12;
    int oz = t % 12;   t /= 12;
    int d  = t % DI;
    int b  = t / DI;

    const float* src = g_xs + ((long)(b*DI+d))*Lt + CCn;
    const float* wp  = w + d*27;
    float acc = __ldg(bias + d);
#pragma unroll
    for (int kz=0;kz<3;kz++){
        int iz = 2*oz - 1 + kz;
        if ((unsigned)iz >= 24u) continue;
#pragma unroll
        for (int ky=0;ky<3;ky++){
            int iy = 2*oy - 1 + ky;
            if ((unsigned)iy >= 24u) continue;
#pragma unroll
            for (int kx=0;kx<3;kx++){
                int ix = 2*ox - 1 + kx;
                if ((unsigned)ix >= 24u) continue;
                acc = fmaf(src[iz*576 + iy*24 + ix], __ldg(wp + kz*9+ky*3+kx), acc);
            }
        }
    }
    g_dxc[idx] = acc;
}

__global__ void zero_fc_kernel()
{
    int i = blockIdx.x*256 + threadIdx.x;
    if (i < Bb*DI*DI) g_fcacc[i] = 0.0f;
}

// silu(fcacc + bias[j]) -> xs[b][j][i] for i < CCn
__global__ void fc_epi_kernel(const float* __restrict__ fcb)
{
    int idx = blockIdx.x*256 + threadIdx.x;
    if (idx >= Bb*DI*DI) return;
    int b   = idx / (DI*DI);
    int rem = idx - b*DI*DI;
    int j   = rem / DI;
    int i   = rem - j*DI;
    float v = g_fcacc[idx] + __ldg(fcb + j);
    g_xs[((long)(b*DI+j))*Lt + i] = siluf_(v);
}

// ---------------- x_proj: x_dbl[b,c,t] = sum_d xs[b,d,t]*W[c,d] ----------------
__global__ __launch_bounds__(128)
void xproj_kernel(const float* __restrict__ W)
{
    __shared__ float sw[32*44];
    int b  = blockIdx.y;
    int tt = blockIdx.x*128 + threadIdx.x;

    float acc[44];
#pragma unroll
    for (int c=0;c<44;c++) acc[c]=0.0f;

    for (int d0=0; d0<DI; d0+=32){
        __syncthreads();
        for (int i=threadIdx.x; i<32*44; i+=128){
            int dd = i/44, c = i - dd*44;
            sw[i] = W[c*DI + d0 + dd];
        }
        __syncthreads();
#pragma unroll 4
        for (int dd=0; dd<32; dd++){
            float xv = g_xs[((long)(b*DI + d0 + dd))*Lt + tt];
            const float* wr = &sw[dd*44];
#pragma unroll
            for (int c=0;c<44;c++) acc[c] = fmaf(wr[c], xv, acc[c]);
        }
    }
#pragma unroll
    for (int c=0;c<12;c++) g_dts[((long)(b*DR+c))*Lt + tt] = acc[c];
    long tb = ((long)b*Lt + tt)*NS;
#pragma unroll
    for (int n=0;n<NS;n++) g_BsT[tb+n] = acc[12+n];
#pragma unroll
    for (int n=0;n<NS;n++) g_CsT[tb+n] = acc[28+n];
}

// ---------------- delta: softplus(dts^T dtw + dtb) ----------------
__global__ __launch_bounds__(128)
void delta_kernel(const float* __restrict__ dtw, const float* __restrict__ dtb)
{
    __shared__ float sw[DI*DR];
    __shared__ float sb[DI];
    int b  = blockIdx.y;
    int tt = blockIdx.x*128 + threadIdx.x;

    for (int i=threadIdx.x; i<DI*DR; i+=128) sw[i] = dtw[i];
    for (int i=threadIdx.x; i<DI;    i+=128) sb[i] = dtb[i];

    float rd[DR];
#pragma unroll
    for (int r=0;r<DR;r++) rd[r] = g_dts[((long)(b*DR+r))*Lt + tt];
    __syncthreads();

    for (int d=0; d<DI; d++){
        float acc = sb[d];
        const float* wr = &sw[d*DR];
#pragma unroll
        for (int r=0;r<DR;r++) acc = fmaf(wr[r], rd[r], acc);
        g_delta[((long)(b*DI+d))*Lt + tt] = softplusf_(acc);
    }
}

// ---------------- scan pass1: within-chunk scan from h=0; also sum(delta) ----------------
__global__ __launch_bounds__(256)
void scan_pass1(const float* __restrict__ A_logs)
{
    int gid = blockIdx.x*256 + threadIdx.x;  // < NCHUNK*Bb*DI*NS
    int n  = gid & 15;
    int r  = gid >> 4;                       // (c*Bb+b)*DI + d
    int d  = r % DI;
    int r2 = r / DI;                         // c*Bb + b
    int b  = r2 & 1;
    int c  = r2 >> 1;

    float Adn = -expf(__ldg(A_logs + d*NS + n));
    long  off = ((long)(b*DI+d))*Lt + c*CLEN;
    const float* dptr = g_delta + off;
    const float* uptr = g_xs    + off;
    const float* bptr = g_BsT   + ((long)b*Lt + c*CLEN)*NS + n;

    float h = 0.0f, ds = 0.0f;
#pragma unroll 4
    for (int i=0;i<CLEN;i++){
        float dlt = __ldg(dptr+i);
        float uu  = __ldg(uptr+i);
        float bb  = __ldg(bptr + i*NS);
        float dA  = __expf(dlt * Adn);
        h  = fmaf(dA, h, dlt*uu*bb);
        ds += dlt;
    }
    g_hend[gid] = h;
    if (n==0) g_dsum[r2*DI + d] = ds;
}

// ---------------- scan pass2: combine across chunks ----------------
__global__ __launch_bounds__(256)
void scan_pass2(const float* __restrict__ A_logs)
{
    int idx = blockIdx.x*256 + threadIdx.x;  // < Bb*DI*NS
    int n = idx & 15;
    int bd = idx >> 4;
    int d = bd % DI;
    int b = bd / DI;
    float Adn = -expf(__ldg(A_logs + d*NS + n));

    float h = 0.0f;
    for (int c=0;c<NCHUNK;c++){
        g_hinit[c*(Bb*DI*NS) + idx] = h;
        float ds = g_dsum[(c*Bb+b)*DI + d];
        float ap = __expf(Adn * ds);
        h = fmaf(ap, h, g_hend[c*(Bb*DI*NS) + idx]);
    }
}

// ---------------- scan pass3: replay with carry-in, produce y ----------------
__global__ __launch_bounds__(256)
void scan_pass3(const float* __restrict__ A_logs, const float* __restrict__ Ds)
{
    int gid = blockIdx.x*256 + threadIdx.x;  // < (NCHUNK-4)*Bb*DI*NS
    int n  = gid & 15;
    int r  = gid >> 4;
    int d  = r % DI;
    int r2 = r / DI;
    int b  = r2 & 1;
    int c  = (r2 >> 1) + 4;                  // output chunks only

    float Adn = -expf(__ldg(A_logs + d*NS + n));
    long  off = ((long)(b*DI+d))*Lt + c*CLEN;
    const float* dptr = g_delta + off;
    const float* uptr = g_xs    + off;
    const float* bptr = g_BsT   + ((long)b*Lt + c*CLEN)*NS + n;
    const float* cptr = g_CsT   + ((long)b*Lt + c*CLEN)*NS + n;

    float h   = g_hinit[c*(Bb*DI*NS) + (b*DI+d)*NS + n];
    float Dsd = __ldg(Ds + d);
    float* yrow = g_y2 + ((long)b*Ls + (c*CLEN - CCn))*DI + d;

    for (int i=0;i<CLEN;i++){
        float dlt = __ldg(dptr+i);
        float uu  = __ldg(uptr+i);
        float bb  = __ldg(bptr + i*NS);
        float dA  = __expf(dlt * Adn);
        h = fmaf(dA, h, dlt*uu*bb);
        float p = h * __ldg(cptr + i*NS);
        p += __shfl_xor_sync(0xffffffffu, p, 8, 16);
        p += __shfl_xor_sync(0xffffffffu, p, 4, 16);
        p += __shfl_xor_sync(0xffffffffu, p, 2, 16);
        p += __shfl_xor_sync(0xffffffffu, p, 1, 16);
        if (n==0) yrow[(long)i*DI] = fmaf(Dsd, uu, p);
    }
}

// ---------------- layernorm + gate ----------------
__global__ __launch_bounds__(128)
void ln_gate_kernel(const float* __restrict__ lng, const float* __restrict__ lnb)
{
    int row = blockIdx.x;                    // b*Ls + l
    int tid = threadIdx.x;
    long base = (long)row*DI;

    float v0 = g_y2[base + tid];
    float v1 = g_y2[base + tid + 128];
    float v2 = g_y2[base + tid + 256];
    float s  = v0+v1+v2;
    float sq = v0*v0 + v1*v1 + v2*v2;
#pragma unroll
    for (int o=16;o>0;o>>=1){
        s  += __shfl_xor_sync(0xffffffffu, s,  o);
        sq += __shfl_xor_sync(0xffffffffu, sq, o);
    }
    __shared__ float rs[4], rq[4];
    if ((tid&31)==0){ rs[tid>>5]=s; rq[tid>>5]=sq; }
    __syncthreads();
    s  = rs[0]+rs[1]+rs[2]+rs[3];
    sq = rq[0]+rq[1]+rq[2]+rq[3];
    float mu  = s  * (1.0f/DI);
    float var = sq * (1.0f/DI) - mu*mu;
    float inv = rsqrtf(var + 1e-5f);

    float vv[3] = {v0,v1,v2};
#pragma unroll
    for (int k=0;k<3;k++){
        int d = tid + k*128;
        float gn = fmaf((vv[k]-mu)*inv, __ldg(lng+d), __ldg(lnb+d));
        float zv = g_z[base + d];
        g_gate[base + d] = gn * zv * sigmoidf_(zv);
    }
}

// ---------------- launch ----------------
extern "C" void kernel_launch(void* const* d_in, const int* in_sizes, int n_in,
                              void* d_out, int out_size)
{
    const float* x           = (const float*)d_in[0];
    const float* in_proj_w   = (const float*)d_in[1];
    const float* conv3d_w    = (const float*)d_in[2];
    const float* conv3d_b    = (const float*)d_in[3];
    const float* depth_conv_w= (const float*)d_in[4];
    const float* depth_conv_b= (const float*)d_in[5];
    const float* depth_fc_w  = (const float*)d_in[6];
    const float* depth_fc_b  = (const float*)d_in[7];
    const float* x_proj_w    = (const float*)d_in[8];
    const float* dt_projs_w  = (const float*)d_in[9];
    const float* dt_projs_b  = (const float*)d_in[10];
    const float* A_logs      = (const float*)d_in[11];
    const float* Ds          = (const float*)d_in[12];
    const float* ln_g        = (const float*)d_in[13];
    const float* ln_b        = (const float*)d_in[14];
    const float* out_proj_w  = (const float*)d_in[15];
    float* out = (float*)d_out;

    float *p_dxc=nullptr, *p_fcacc=nullptr, *p_gate=nullptr;
    cudaGetSymbolAddress((void**)&p_dxc,   g_dxc);
    cudaGetSymbolAddress((void**)&p_fcacc, g_fcacc);
    cudaGetSymbolAddress((void**)&p_gate,  g_gate);

    // 1) in_proj GEMM: (27648x192) @ (768x192)^T, scatter into x1t / z
    gemm128x64<1><<<dim3(768/64, NM/128, 1), 256>>>(
        x, in_proj_w, nullptr, 768, Cc, Cc, 0, 0, 0, 1);

    // 2) conv1 (+silu) -> xs[:, :, CCn:]
    conv1_kernel<<<dim3(Bb*DI, 2), 256>>>(conv3d_w, conv3d_b);

    // 3) conv2 stride-2 (+bias) -> dxc
    conv2_kernel<<<(Bb*DI*DOUT)/256, 256>>>(depth_conv_w, depth_conv_b);

    // 4) depth FC: split-K=6 atomic GEMM  fcacc[b][j][i] = sum_k W[j,k]*dxc[b,i,k]
    zero_fc_kernel<<<(Bb*DI*DI)/256, 256>>>();
    gemm128x64<2><<<dim3(DI/64, DI/128, Bb*6), 256>>>(
        depth_fc_w, p_dxc, p_fcacc, DI, DOUT, DOUT/6,
        0, (long)DI*DOUT, (long)DI*DI, 6);
    fc_epi_kernel<<<(Bb*DI*DI)/256, 256>>>(depth_fc_b);

    // 5) x_proj -> dts / BsT / CsT
    xproj_kernel<<<dim3(Lt/128, Bb), 128>>>(x_proj_w);

    // 6) delta = softplus(dt_proj(dts) + dtb)
    delta_kernel<<<dim3(Lt/128, Bb), 128>>>(dt_projs_w, dt_projs_b);

    // 7) chunked selective scan
    scan_pass1<<<(NCHUNK*Bb*DI*NS)/256, 256>>>(A_logs);
    scan_pass2<<<(Bb*DI*NS)/256, 256>>>(A_logs);
    scan_pass3<<<((NCHUNK-4)*Bb*DI*NS)/256, 256>>>(A_logs, Ds);

    // 8) layernorm + silu(z) gate
    ln_gate_kernel<<<Bb*Ls, 128>>>(ln_g, ln_b);

    // 9) out_proj GEMM: (27648x384) @ (192x384)^T -> out
    gemm128x64<0><<<dim3(Cc/64, NM/128, 1), 256>>>(
        p_gate, out_proj_w, out, Cc, DI, DI, 0, 0, 0, 1);
}

// round 13
// speedup vs baseline: 1.2399x; 1.2399x over previous
#include <cuda_runtime.h>
#include <cuda_bf16.h>
#include <cstdint>

// ---------------- problem constants ----------------
#define Bb      2
#define Cc      192
#define DI      384          // d_inner
#define NS      16           // d_state
#define DR      12           // dt_rank
#define Ls      13824        // 24^3
#define CCn     384          // prefix timesteps from depth branch
#define Lt      14208        // CCn + Ls
#define NM      27648        // B*Ls (GEMM rows)
#define NCHUNK  148
#define CLEN    96           // NCHUNK*CLEN == Lt
#define DOUT    1728         // 12^3

// ---------------- scratch (static device globals; no runtime alloc) ----------------
__device__ float g_x1t  [Bb*DI*Ls];        // (b,d,l)  conv input
__device__ float g_z    [Bb*Ls*DI];        // (b,l,d)  gate input
__device__ float g_xs   [Bb*DI*Lt];        // (b,d,t)  concat sequence
__device__ float g_dxc  [Bb*DI*DOUT];      // (b,d,1728)
__device__ float g_fcacc[Bb*DI*DI];        // (b,j,i) split-K accumulator
__device__ float g_dts  [Bb*DR*Lt];        // (b,r,t)
__device__ float g_BsT  [Bb*Lt*NS];        // (b,t,n)
__device__ float g_CsT  [Bb*Lt*NS];        // (b,t,n)
__device__ float g_delta[Bb*DI*Lt];        // (b,d,t)
__device__ float g_hend [NCHUNK*Bb*DI*NS];
__device__ float g_hinit[NCHUNK*Bb*DI*NS];
__device__ float g_dsum [NCHUNK*Bb*DI];
__device__ float g_y2   [Bb*Ls*DI];        // (b,l,d)
__device__ float g_gate [Bb*Ls*DI];        // (b,l,d)

// ---------------- helpers ----------------
__device__ __forceinline__ float sigmoidf_(float x){ return 1.0f/(1.0f+__expf(-x)); }
__device__ __forceinline__ float siluf_(float x){ return x*sigmoidf_(x); }
__device__ __forceinline__ float softplusf_(float x){
    return fmaxf(x,0.0f) + log1pf(__expf(-fabsf(x)));
}

#define SMEM_SWIZZLE_128B(byte_offset) \
    ((byte_offset) ^ (((byte_offset) >> 3) & 0x70))

__device__ __forceinline__ uint32_t smem_u32(const void* p) {
    uint32_t a;
    asm("{ .reg .u64 t; cvta.to.shared.u64 t, %1; cvt.u32.u64 %0, t; }"
        : "=r"(a) : "l"(p));
    return a;
}
__device__ __forceinline__ void ldsm_x4(uint32_t (&r)[4], uint32_t addr){
    asm volatile("ldmatrix.sync.aligned.m8n8.x4.shared.b16 {%0,%1,%2,%3}, [%4];"
        : "=r"(r[0]),"=r"(r[1]),"=r"(r[2]),"=r"(r[3]) : "r"(addr));
}
__device__ __forceinline__ void mma16816(float (&d)[4], const uint32_t (&a)[4],
                                         uint32_t b0, uint32_t b1){
    asm volatile("mma.sync.aligned.m16n8k16.row.col.f32.bf16.bf16.f32 "
        "{%0,%1,%2,%3},{%4,%5,%6,%7},{%8,%9},{%0,%1,%2,%3};"
        : "+f"(d[0]),"+f"(d[1]),"+f"(d[2]),"+f"(d[3])
        : "r"(a[0]),"r"(a[1]),"r"(a[2]),"r"(a[3]), "r"(b0),"r"(b1));
}

__device__ __forceinline__ void bf16_split2(float a, float b, uint32_t &hi, uint32_t &lo)
{
    __nv_bfloat16 ha = __float2bfloat16_rn(a);
    __nv_bfloat16 hb = __float2bfloat16_rn(b);
    float ra = a - __bfloat162float(ha);
    float rb = b - __bfloat162float(hb);
    __nv_bfloat162 H; H.x = ha; H.y = hb;
    __nv_bfloat162 L = __floats2bfloat162_rn(ra, rb);
    hi = *reinterpret_cast<uint32_t*>(&H);
    lo = *reinterpret_cast<uint32_t*>(&L);
}

// ---------------- HMMA GEMM: C[m,n] = sum_k A[m,k]*W[n,k] ----------------
// BM=128, BN=64, BK=64, 256 threads (8 warps, warp tile 32x32).
// bf16 hi/lo split: hi*hi + lo*hi + hi*lo, fp32 accumulate.
// EPI 0: plain row-major store.  EPI 1: in_proj scatter (x1t / z).
#define SA_HI 0
#define SA_LO 16384
#define SB_HI 32768
#define SB_LO 40960

template<int EPI>
__global__ __launch_bounds__(256)
void hgemm_kernel(const float* __restrict__ A, const float* __restrict__ Bw,
                  float* __restrict__ C, int N, int K)
{
    __shared__ __align__(1024) uint8_t sbuf[49152];
    const uint32_t sb = smem_u32(sbuf);

    const int tid  = threadIdx.x;
    const int lane = tid & 31;
    const int wid  = tid >> 5;
    const int wm   = wid & 3;           // 4 warps along M
    const int wn   = wid >> 2;          // 2 warps along N
    const int mbase = blockIdx.y * 128;
    const int nbase = blockIdx.x * 64;

    float acc[2][4][4];
#pragma unroll
    for (int i=0;i<2;i++)
#pragma unroll
        for (int j=0;j<4;j++)
#pragma unroll
            for (int q=0;q<4;q++) acc[i][j][q]=0.0f;

    // ldmatrix per-lane address components (row within tile, 16B chunk select)
    const int lrow = lane & 15;         // row within 16-row tile
    const int lhik = (lane >> 4) * 16;  // 0 or 16 bytes (k halves)

    const int nch = K >> 6;
    for (int c = 0; c < nch; ++c) {
        __syncthreads();
        // ---- A chunk: 128 rows x 64 cols fp32 -> bf16 hi/lo, swizzled ----
#pragma unroll
        for (int it = 0; it < 4; ++it) {
            int idx = tid + it*256;          // 0..1023
            int row = idx >> 3;
            int grp = idx & 7;
            const float* src = A + (long)(mbase+row)*K + c*64 + grp*8;
            float4 v0 = *(const float4*)src;
            float4 v1 = *(const float4*)(src+4);
            uint4 H, L;
            bf16_split2(v0.x, v0.y, H.x, L.x);
            bf16_split2(v0.z, v0.w, H.y, L.y);
            bf16_split2(v1.x, v1.y, H.z, L.z);
            bf16_split2(v1.z, v1.w, H.w, L.w);
            uint32_t sw = SMEM_SWIZZLE_128B((uint32_t)(row*128 + grp*16));
            *(uint4*)(sbuf + SA_HI + sw) = H;
            *(uint4*)(sbuf + SA_LO + sw) = L;
        }
        // ---- B chunk: 64 rows x 64 cols ----
#pragma unroll
        for (int it = 0; it < 2; ++it) {
            int idx = tid + it*256;          // 0..511
            int row = idx >> 3;
            int grp = idx & 7;
            const float* src = Bw + (long)(nbase+row)*K + c*64 + grp*8;
            float4 v0 = *(const float4*)src;
            float4 v1 = *(const float4*)(src+4);
            uint4 H, L;
            bf16_split2(v0.x, v0.y, H.x, L.x);
            bf16_split2(v0.z, v0.w, H.y, L.y);
            bf16_split2(v1.x, v1.y, H.z, L.z);
            bf16_split2(v1.z, v1.w, H.w, L.w);
            uint32_t sw = SMEM_SWIZZLE_128B((uint32_t)(row*128 + grp*16));
            *(uint4*)(sbuf + SB_HI + sw) = H;
            *(uint4*)(sbuf + SB_LO + sw) = L;
        }
        __syncthreads();

        // ---- compute: 4 k16 steps ----
#pragma unroll
        for (int kk = 0; kk < 4; ++kk) {
            const uint32_t kcol = (uint32_t)(kk*32 + lhik);

            uint32_t ah[2][4], al[2][4];
#pragma unroll
            for (int mi = 0; mi < 2; ++mi) {
                uint32_t roff = (uint32_t)((wm*32 + mi*16 + lrow)*128) + kcol;
                uint32_t sw   = SMEM_SWIZZLE_128B(roff);
                ldsm_x4(ah[mi], sb + SA_HI + sw);
                ldsm_x4(al[mi], sb + SA_LO + sw);
            }
            // B: two x4 loads cover 32 n-rows (4 n-tiles of 8), per precision
            uint32_t bh[2][4], bl[2][4];
#pragma unroll
            for (int p = 0; p < 2; ++p) {
                uint32_t roff = (uint32_t)((wn*32 + p*16 + lrow)*128) + kcol;
                uint32_t sw   = SMEM_SWIZZLE_128B(roff);
                ldsm_x4(bh[p], sb + SB_HI + sw);
                ldsm_x4(bl[p], sb + SB_LO + sw);
            }
            // n-tile ni (0..3): pair p = ni>>1, fragment = {r[ni&1], r[(ni&1)+2]}
#pragma unroll
            for (int mi = 0; mi < 2; ++mi) {
#pragma unroll
                for (int ni = 0; ni < 4; ++ni) {
                    int p = ni >> 1, s = ni & 1;
                    mma16816(acc[mi][ni], ah[mi], bh[p][s], bh[p][s+2]);
                    mma16816(acc[mi][ni], al[mi], bh[p][s], bh[p][s+2]);
                    mma16816(acc[mi][ni], ah[mi], bl[p][s], bl[p][s+2]);
                }
            }
        }
    }

    // ---- epilogue ----
    const int r0 = mbase + wm*32 + (lane >> 2);   // + mi*16, +8 for upper pair
    const int c0 = nbase + wn*32 + (lane & 3)*2;  // + ni*8

    if (EPI == 0) {
#pragma unroll
        for (int mi = 0; mi < 2; ++mi) {
#pragma unroll
            for (int ni = 0; ni < 4; ++ni) {
                int row = r0 + mi*16;
                int col = c0 + ni*8;
                float2 v01 = make_float2(acc[mi][ni][0], acc[mi][ni][1]);
                float2 v23 = make_float2(acc[mi][ni][2], acc[mi][ni][3]);
                *(float2*)(C + (long)row*N + col)     = v01;
                *(float2*)(C + (long)(row+8)*N + col) = v23;
            }
        }
    } else {
        const int b = mbase / Ls;                 // block never crosses batch
        const int lb = mbase - b*Ls;
#pragma unroll
        for (int mi = 0; mi < 2; ++mi) {
#pragma unroll
            for (int ni = 0; ni < 4; ++ni) {
                int l0  = lb + wm*32 + mi*16 + (lane >> 2);
                int col = c0 + ni*8;
                if (col < DI) {
                    g_x1t[((long)(b*DI + col  ))*Ls + l0    ] = acc[mi][ni][0];
                    g_x1t[((long)(b*DI + col+1))*Ls + l0    ] = acc[mi][ni][1];
                    g_x1t[((long)(b*DI + col  ))*Ls + l0 + 8] = acc[mi][ni][2];
                    g_x1t[((long)(b*DI + col+1))*Ls + l0 + 8] = acc[mi][ni][3];
                } else {
                    int d = col - DI;
                    *(float2*)(g_z + ((long)b*Ls + l0    )*DI + d) =
                        make_float2(acc[mi][ni][0], acc[mi][ni][1]);
                    *(float2*)(g_z + ((long)b*Ls + l0 + 8)*DI + d) =
                        make_float2(acc[mi][ni][2], acc[mi][ni][3]);
                }
            }
        }
    }
}

// ---------------- fp32 SGEMM (kept for depth_fc split-K only) ----------------
template<int EPI>
__global__ __launch_bounds__(256)
void gemm128x64(const float* __restrict__ A, const float* __restrict__ Bw,
                float* __restrict__ C, int N, int Krow, int Kc,
                long sA, long sB, long sC, int ksplit)
{
    int bz    = blockIdx.z;
    int batch = bz / ksplit;
    int ks    = bz - batch*ksplit;
    long k0   = (long)ks * Kc;

    const float* Ab = A  + batch*sA + (long)blockIdx.y*128*Krow + k0;
    const float* Bc = Bw + batch*sB + (long)blockIdx.x*64 *Krow + k0;

    __shared__ float As[16][128];
    __shared__ float Bs[16][64];

    int tid  = threadIdx.x;
    int lrow = tid >> 2;
    int lk   = (tid & 3) << 2;
    int tx   = tid & 15;
    int ty   = tid >> 4;

    float acc[8][4];
#pragma unroll
    for (int i=0;i<8;i++)
#pragma unroll
        for (int j=0;j<4;j++) acc[i][j]=0.0f;

    for (int kt = 0; kt < Kc; kt += 16) {
        float4 a0 = *(const float4*)(Ab + (long)lrow     *Krow + kt + lk);
        float4 a1 = *(const float4*)(Ab + (long)(lrow+64)*Krow + kt + lk);
        float4 b0 = *(const float4*)(Bc + (long)lrow     *Krow + kt + lk);
        __syncthreads();
        As[lk+0][lrow]=a0.x; As[lk+1][lrow]=a0.y; As[lk+2][lrow]=a0.z; As[lk+3][lrow]=a0.w;
        As[lk+0][lrow+64]=a1.x; As[lk+1][lrow+64]=a1.y; As[lk+2][lrow+64]=a1.z; As[lk+3][lrow+64]=a1.w;
        Bs[lk+0][lrow]=b0.x; Bs[lk+1][lrow]=b0.y; Bs[lk+2][lrow]=b0.z; Bs[lk+3][lrow]=b0.w;
        __syncthreads();
#pragma unroll
        for (int k=0;k<16;k++){
            float4 av0 = *(const float4*)&As[k][ty*4];
            float4 av1 = *(const float4*)&As[k][64+ty*4];
            float4 bv  = *(const float4*)&Bs[k][tx*4];
            float am[8] = {av0.x,av0.y,av0.z,av0.w, av1.x,av1.y,av1.z,av1.w};
            float bn[4] = {bv.x,bv.y,bv.z,bv.w};
#pragma unroll
            for (int i=0;i<8;i++)
#pragma unroll
                for (int j=0;j<4;j++)
                    acc[i][j] = fmaf(am[i], bn[j], acc[i][j]);
        }
    }

    int mbase = blockIdx.y*128;
    int nbase = blockIdx.x*64 + tx*4;
#pragma unroll
    for (int i=0;i<8;i++){
        int mg = mbase + ((i<4) ? (ty*4+i) : (64+ty*4+(i-4)));
        float* cp = C + batch*sC + (long)mg*N + nbase;
        if (EPI==2){
            atomicAdd(cp+0, acc[i][0]);
            atomicAdd(cp+1, acc[i][1]);
            atomicAdd(cp+2, acc[i][2]);
            atomicAdd(cp+3, acc[i][3]);
        } else {
            float4 v = make_float4(acc[i][0],acc[i][1],acc[i][2],acc[i][3]);
            *(float4*)cp = v;
        }
    }
}

// ---------------- conv1: depthwise 3x3x3, stride 1, pad 1, + bias + silu -> xs[:, :, CCn:] ----
__global__ __launch_bounds__(256)
void conv1_kernel(const float* __restrict__ w, const float* __restrict__ bias)
{
    int bd   = blockIdx.x;
    int d    = bd % DI;
    int slab = blockIdx.y;
    int zbase = slab*12;

    __shared__ float sm[14*576];
    const float* src = g_x1t + (long)bd*Ls;
    int tid = threadIdx.x;

    for (int i=tid; i<14*576; i+=256){
        int zp = i/576;
        int z  = zbase - 1 + zp;
        sm[i] = (z>=0 && z<24) ? src[z*576 + (i - zp*576)] : 0.0f;
    }
    float wr[27];
#pragma unroll
    for (int i=0;i<27;i++) wr[i] = __ldg(w + d*27 + i);
    float cb = __ldg(bias + d);
    __syncthreads();

    float* dst = g_xs + (long)bd*Lt + CCn + zbase*576;
    for (int o=tid; o<12*576; o+=256){
        int ozl = o/576;
        int rem = o - ozl*576;
        int oy  = rem/24;
        int ox  = rem - oy*24;
        float acc = cb;
#pragma unroll
        for (int kz=0;kz<3;kz++){
            const float* p = &sm[(ozl+kz)*576];
#pragma unroll
            for (int ky=0;ky<3;ky++){
                int iy = oy + ky - 1;
                if ((unsigned)iy >= 24u) continue;
#pragma unroll
                for (int kx=0;kx<3;kx++){
                    int ix = ox + kx - 1;
                    if ((unsigned)ix >= 24u) continue;
                    acc = fmaf(p[iy*24+ix], wr[kz*9+ky*3+kx], acc);
                }
            }
        }
        dst[o] = siluf_(acc);
    }
}

// ---------------- conv2: depthwise 3x3x3, stride 2, pad 1, + bias -> g_dxc ----------------
__global__ void conv2_kernel(const float* __restrict__ w, const float* __restrict__ bias)
{
    int idx = blockIdx.x*256 + threadIdx.x;
    if (idx >= Bb*DI*DOUT) return;
    int ox = idx % 12; int t = idx/12;
    int oy = t % 12;   t /= 12;
    int oz = t % 12;   t /= 12;
    int d  = t % DI;
    int b  = t / DI;

    const float* src = g_xs + ((long)(b*DI+d))*Lt + CCn;
    const float* wp  = w + d*27;
    float acc = __ldg(bias + d);
#pragma unroll
    for (int kz=0;kz<3;kz++){
        int iz = 2*oz - 1 + kz;
        if ((unsigned)iz >= 24u) continue;
#pragma unroll
        for (int ky=0;ky<3;ky++){
            int iy = 2*oy - 1 + ky;
            if ((unsigned)iy >= 24u) continue;
#pragma unroll
            for (int kx=0;kx<3;kx++){
                int ix = 2*ox - 1 + kx;
                if ((unsigned)ix >= 24u) continue;
                acc = fmaf(src[iz*576 + iy*24 + ix], __ldg(wp + kz*9+ky*3+kx), acc);
            }
        }
    }
    g_dxc[idx] = acc;
}

__global__ void zero_fc_kernel()
{
    int i = blockIdx.x*256 + threadIdx.x;
    if (i < Bb*DI*DI) g_fcacc[i] = 0.0f;
}

__global__ void fc_epi_kernel(const float* __restrict__ fcb)
{
    int idx = blockIdx.x*256 + threadIdx.x;
    if (idx >= Bb*DI*DI) return;
    int b   = idx / (DI*DI);
    int rem = idx - b*DI*DI;
    int j   = rem / DI;
    int i   = rem - j*DI;
    float v = g_fcacc[idx] + __ldg(fcb + j);
    g_xs[((long)(b*DI+j))*Lt + i] = siluf_(v);
}

// ---------------- x_proj ----------------
__global__ __launch_bounds__(128)
void xproj_kernel(const float* __restrict__ W)
{
    __shared__ float sw[32*44];
    int b  = blockIdx.y;
    int tt = blockIdx.x*128 + threadIdx.x;

    float acc[44];
#pragma unroll
    for (int c=0;c<44;c++) acc[c]=0.0f;

    for (int d0=0; d0<DI; d0+=32){
        __syncthreads();
        for (int i=threadIdx.x; i<32*44; i+=128){
            int dd = i/44, c = i - dd*44;
            sw[i] = W[c*DI + d0 + dd];
        }
        __syncthreads();
#pragma unroll 4
        for (int dd=0; dd<32; dd++){
            float xv = g_xs[((long)(b*DI + d0 + dd))*Lt + tt];
            const float* wr = &sw[dd*44];
#pragma unroll
            for (int c=0;c<44;c++) acc[c] = fmaf(wr[c], xv, acc[c]);
        }
    }
#pragma unroll
    for (int c=0;c<12;c++) g_dts[((long)(b*DR+c))*Lt + tt] = acc[c];
    long tb = ((long)b*Lt + tt)*NS;
#pragma unroll
    for (int n=0;n<NS;n++) g_BsT[tb+n] = acc[12+n];
#pragma unroll
    for (int n=0;n<NS;n++) g_CsT[tb+n] = acc[28+n];
}

// ---------------- delta ----------------
__global__ __launch_bounds__(128)
void delta_kernel(const float* __restrict__ dtw, const float* __restrict__ dtb)
{
    __shared__ float sw[DI*DR];
    __shared__ float sb[DI];
    int b  = blockIdx.y;
    int tt = blockIdx.x*128 + threadIdx.x;

    for (int i=threadIdx.x; i<DI*DR; i+=128) sw[i] = dtw[i];
    for (int i=threadIdx.x; i<DI;    i+=128) sb[i] = dtb[i];

    float rd[DR];
#pragma unroll
    for (int r=0;r<DR;r++) rd[r] = g_dts[((long)(b*DR+r))*Lt + tt];
    __syncthreads();

    for (int d=0; d<DI; d++){
        float acc = sb[d];
        const float* wr = &sw[d*DR];
#pragma unroll
        for (int r=0;r<DR;r++) acc = fmaf(wr[r], rd[r], acc);
        g_delta[((long)(b*DI+d))*Lt + tt] = softplusf_(acc);
    }
}

// ---------------- scan pass1 ----------------
__global__ __launch_bounds__(256)
void scan_pass1(const float* __restrict__ A_logs)
{
    int gid = blockIdx.x*256 + threadIdx.x;
    int n  = gid & 15;
    int r  = gid >> 4;
    int d  = r % DI;
    int r2 = r / DI;
    int b  = r2 & 1;
    int c  = r2 >> 1;

    float Adn = -expf(__ldg(A_logs + d*NS + n));
    long  off = ((long)(b*DI+d))*Lt + c*CLEN;
    const float* dptr = g_delta + off;
    const float* uptr = g_xs    + off;
    const float* bptr = g_BsT   + ((long)b*Lt + c*CLEN)*NS + n;

    float h = 0.0f, ds = 0.0f;
#pragma unroll 4
    for (int i=0;i<CLEN;i++){
        float dlt = __ldg(dptr+i);
        float uu  = __ldg(uptr+i);
        float bb  = __ldg(bptr + i*NS);
        float dA  = __expf(dlt * Adn);
        h  = fmaf(dA, h, dlt*uu*bb);
        ds += dlt;
    }
    g_hend[gid] = h;
    if (n==0) g_dsum[r2*DI + d] = ds;
}

// ---------------- scan pass2 ----------------
__global__ __launch_bounds__(256)
void scan_pass2(const float* __restrict__ A_logs)
{
    int idx = blockIdx.x*256 + threadIdx.x;
    int n = idx & 15;
    int bd = idx >> 4;
    int d = bd % DI;
    int b = bd / DI;
    float Adn = -expf(__ldg(A_logs + d*NS + n));

    float h = 0.0f;
    for (int c=0;c<NCHUNK;c++){
        g_hinit[c*(Bb*DI*NS) + idx] = h;
        float ds = g_dsum[(c*Bb+b)*DI + d];
        float ap = __expf(Adn * ds);
        h = fmaf(ap, h, g_hend[c*(Bb*DI*NS) + idx]);
    }
}

// ---------------- scan pass3 ----------------
__global__ __launch_bounds__(256)
void scan_pass3(const float* __restrict__ A_logs, const float* __restrict__ Ds)
{
    int gid = blockIdx.x*256 + threadIdx.x;
    int n  = gid & 15;
    int r  = gid >> 4;
    int d  = r % DI;
    int r2 = r / DI;
    int b  = r2 & 1;
    int c  = (r2 >> 1) + 4;

    float Adn = -expf(__ldg(A_logs + d*NS + n));
    long  off = ((long)(b*DI+d))*Lt + c*CLEN;
    const float* dptr = g_delta + off;
    const float* uptr = g_xs    + off;
    const float* bptr = g_BsT   + ((long)b*Lt + c*CLEN)*NS + n;
    const float* cptr = g_CsT   + ((long)b*Lt + c*CLEN)*NS + n;

    float h   = g_hinit[c*(Bb*DI*NS) + (b*DI+d)*NS + n];
    float Dsd = __ldg(Ds + d);
    float* yrow = g_y2 + ((long)b*Ls + (c*CLEN - CCn))*DI + d;

    for (int i=0;i<CLEN;i++){
        float dlt = __ldg(dptr+i);
        float uu  = __ldg(uptr+i);
        float bb  = __ldg(bptr + i*NS);
        float dA  = __expf(dlt * Adn);
        h = fmaf(dA, h, dlt*uu*bb);
        float p = h * __ldg(cptr + i*NS);
        p += __shfl_xor_sync(0xffffffffu, p, 8, 16);
        p += __shfl_xor_sync(0xffffffffu, p, 4, 16);
        p += __shfl_xor_sync(0xffffffffu, p, 2, 16);
        p += __shfl_xor_sync(0xffffffffu, p, 1, 16);
        if (n==0) yrow[(long)i*DI] = fmaf(Dsd, uu, p);
    }
}

// ---------------- layernorm + gate ----------------
__global__ __launch_bounds__(128)
void ln_gate_kernel(const float* __restrict__ lng, const float* __restrict__ lnb)
{
    int row = blockIdx.x;
    int tid = threadIdx.x;
    long base = (long)row*DI;

    float v0 = g_y2[base + tid];
    float v1 = g_y2[base + tid + 128];
    float v2 = g_y2[base + tid + 256];
    float s  = v0+v1+v2;
    float sq = v0*v0 + v1*v1 + v2*v2;
#pragma unroll
    for (int o=16;o>0;o>>=1){
        s  += __shfl_xor_sync(0xffffffffu, s,  o);
        sq += __shfl_xor_sync(0xffffffffu, sq, o);
    }
    __shared__ float rs[4], rq[4];
    if ((tid&31)==0){ rs[tid>>5]=s; rq[tid>>5]=sq; }
    __syncthreads();
    s  = rs[0]+rs[1]+rs[2]+rs[3];
    sq = rq[0]+rq[1]+rq[2]+rq[3];
    float mu  = s  * (1.0f/DI);
    float var = sq * (1.0f/DI) - mu*mu;
    float inv = rsqrtf(var + 1e-5f);

    float vv[3] = {v0,v1,v2};
#pragma unroll
    for (int k=0;k<3;k++){
        int d = tid + k*128;
        float gn = fmaf((vv[k]-mu)*inv, __ldg(lng+d), __ldg(lnb+d));
        float zv = g_z[base + d];
        g_gate[base + d] = gn * zv * sigmoidf_(zv);
    }
}

// ---------------- launch ----------------
extern "C" void kernel_launch(void* const* d_in, const int* in_sizes, int n_in,
                              void* d_out, int out_size)
{
    const float* x           = (const float*)d_in[0];
    const float* in_proj_w   = (const float*)d_in[1];
    const float* conv3d_w    = (const float*)d_in[2];
    const float* conv3d_b    = (const float*)d_in[3];
    const float* depth_conv_w= (const float*)d_in[4];
    const float* depth_conv_b= (const float*)d_in[5];
    const float* depth_fc_w  = (const float*)d_in[6];
    const float* depth_fc_b  = (const float*)d_in[7];
    const float* x_proj_w    = (const float*)d_in[8];
    const float* dt_projs_w  = (const float*)d_in[9];
    const float* dt_projs_b  = (const float*)d_in[10];
    const float* A_logs      = (const float*)d_in[11];
    const float* Ds          = (const float*)d_in[12];
    const float* ln_g        = (const float*)d_in[13];
    const float* ln_b        = (const float*)d_in[14];
    const float* out_proj_w  = (const float*)d_in[15];
    float* out = (float*)d_out;

    float *p_dxc=nullptr, *p_fcacc=nullptr, *p_gate=nullptr;
    cudaGetSymbolAddress((void**)&p_dxc,   g_dxc);
    cudaGetSymbolAddress((void**)&p_fcacc, g_fcacc);
    cudaGetSymbolAddress((void**)&p_gate,  g_gate);

    // 1) in_proj GEMM (HMMA bf16 hi/lo split), scatter into x1t / z
    hgemm_kernel<1><<<dim3(768/64, NM/128), 256>>>(
        x, in_proj_w, nullptr, 768, Cc);

    // 2) conv1 (+silu) -> xs[:, :, CCn:]
    conv1_kernel<<<dim3(Bb*DI, 2), 256>>>(conv3d_w, conv3d_b);

    // 3) conv2 stride-2 (+bias) -> dxc
    conv2_kernel<<<(Bb*DI*DOUT)/256, 256>>>(depth_conv_w, depth_conv_b);

    // 4) depth FC: split-K=6 atomic fp32 GEMM
    zero_fc_kernel<<<(Bb*DI*DI)/256, 256>>>();
    gemm128x64<2><<<dim3(DI/64, DI/128, Bb*6), 256>>>(
        depth_fc_w, p_dxc, p_fcacc, DI, DOUT, DOUT/6,
        0, (long)DI*DOUT, (long)DI*DI, 6);
    fc_epi_kernel<<<(Bb*DI*DI)/256, 256>>>(depth_fc_b);

    // 5) x_proj -> dts / BsT / CsT
    xproj_kernel<<<dim3(Lt/128, Bb), 128>>>(x_proj_w);

    // 6) delta
    delta_kernel<<<dim3(Lt/128, Bb), 128>>>(dt_projs_w, dt_projs_b);

    // 7) chunked selective scan
    scan_pass1<<<(NCHUNK*Bb*DI*NS)/256, 256>>>(A_logs);
    scan_pass2<<<(Bb*DI*NS)/256, 256>>>(A_logs);
    scan_pass3<<<((NCHUNK-4)*Bb*DI*NS)/256, 256>>>(A_logs, Ds);

    // 8) layernorm + silu(z) gate
    ln_gate_kernel<<<Bb*Ls, 128>>>(ln_g, ln_b);

    // 9) out_proj GEMM (HMMA) -> out
    hgemm_kernel<0><<<dim3(Cc/64, NM/128), 256>>>(
        p_gate, out_proj_w, out, Cc, DI);
}